// round 16
// baseline (speedup 1.0000x reference)
#include <cuda_runtime.h>

// Problem constants (fixed by setup_inputs): B=4, N=M=8192, D=3
constexpr int Bn   = 4;
constexpr int Np   = 8192;
constexpr int NPTS = 2 * Bn * Np;   // 65536 query results
constexpr int NSEG = 2 * Bn;        // 8 segments: cloud x batch
constexpr int GD   = 16;
constexpr int NC   = GD * GD * GD;  // 4096 cells per segment (sort key only)
constexpr int CHSZ = 128;           // points per chunk (equal-count)
constexpr int NCH  = Np / CHSZ;     // 64 chunks per segment
constexpr float HLO  = -6.0f;
constexpr float INVH = 16.0f / 12.0f;

// Scratch (static __device__, no allocs). All rewritten every call.
__device__ float4 g_pts [NSEG * Np];   // cell-sorted, .w = |p|^2
__device__ int    g_idx [NSEG * Np];   // original index of sorted point
__device__ float4 g_clo [NSEG * NCH];  // chunk bbox lo (x,y,z,-)
__device__ float4 g_chi [NSEG * NCH];  // chunk bbox hi
__device__ float  g_mind[NPTS];        // min d2 per (dir, batch, ORIGINAL idx)

__device__ __forceinline__ int cellof(float v) {
    int c = __float2int_rd((v - HLO) * INVH);
    return min(max(c, 0), GD - 1);
}
__device__ __forceinline__ unsigned fkey(float x) {   // order-preserving float->uint
    unsigned u = __float_as_uint(x);
    return u ^ ((unsigned)((int)u >> 31) | 0x80000000u);
}
__device__ __forceinline__ float funkey(unsigned k) {
    return (k & 0x80000000u) ? __uint_as_float(k & 0x7fffffffu)
                             : __uint_as_float(~k);
}
__device__ __forceinline__ unsigned redux_min(unsigned v) {
    unsigned d; asm("redux.sync.min.u32 %0, %1, 0xffffffff;" : "=r"(d) : "r"(v));
    return d;
}
__device__ __forceinline__ unsigned redux_max(unsigned v) {
    unsigned d; asm("redux.sync.max.u32 %0, %1, 0xffffffff;" : "=r"(d) : "r"(v));
    return d;
}

// ---- build: per-segment shared-memory counting sort (ONE kernel) ----

__global__ __launch_bounds__(1024)
void build_sort(const float* __restrict__ src, const float* __restrict__ tgt) {
    __shared__ int cnt[NC];      // counts -> starts -> running cursors
    __shared__ int part[1024];
    const int seg = blockIdx.x;  // 8 blocks
    const int tid = threadIdx.x;
    const float* base = ((seg >> 2) ? tgt : src) + (size_t)(seg & 3) * Np * 3;

#pragma unroll
    for (int k = 0; k < NC / 1024; k++) cnt[tid + k * 1024] = 0;
    __syncthreads();

    // pass 1: count
    for (int k = 0; k < Np / 1024; k++) {
        const float* p = base + (size_t)(tid + k * 1024) * 3;
        atomicAdd(&cnt[(cellof(p[2]) * GD + cellof(p[1])) * GD + cellof(p[0])], 1);
    }
    __syncthreads();

    // scan: thread owns 4 cells; Hillis-Steele over 1024 partials
    int s = 0, c4[4];
#pragma unroll
    for (int k = 0; k < 4; k++) { c4[k] = cnt[tid * 4 + k]; s += c4[k]; }
    part[tid] = s;
    __syncthreads();
    int v = s;
    for (int off = 1; off < 1024; off <<= 1) {
        int u = (tid >= off) ? part[tid - off] : 0;
        __syncthreads();
        v += u;
        part[tid] = v;
        __syncthreads();
    }
    int run = v - s;  // exclusive prefix
#pragma unroll
    for (int k = 0; k < 4; k++) { cnt[tid * 4 + k] = run; run += c4[k]; }
    __syncthreads();

    // pass 2: scatter (order-nondet within cell; harmless, min is set-invariant)
    for (int k = 0; k < Np / 1024; k++) {
        int i = tid + k * 1024;
        const float* p = base + (size_t)i * 3;
        float x = p[0], y = p[1], z = p[2];
        int cell = (cellof(z) * GD + cellof(y)) * GD + cellof(x);
        int slot = atomicAdd(&cnt[cell], 1);
        g_pts[seg * Np + slot] = make_float4(x, y, z, fmaf(x, x, fmaf(y, y, z * z)));
        g_idx[seg * Np + slot] = i;
    }
}

// ---- chunk bboxes: one warp per chunk ----

__global__ void chunk_bbox() {
    const int lane = threadIdx.x & 31;
    const int ci   = (blockIdx.x * blockDim.x + threadIdx.x) >> 5;  // 512 chunks
    float lx = 3.4e38f, ly = 3.4e38f, lz = 3.4e38f;
    float hx = -3.4e38f, hy = -3.4e38f, hz = -3.4e38f;
#pragma unroll
    for (int k = 0; k < CHSZ / 32; k++) {
        float4 p = g_pts[ci * CHSZ + k * 32 + lane];
        lx = fminf(lx, p.x); ly = fminf(ly, p.y); lz = fminf(lz, p.z);
        hx = fmaxf(hx, p.x); hy = fmaxf(hy, p.y); hz = fmaxf(hz, p.z);
    }
    lx = funkey(redux_min(fkey(lx)));
    ly = funkey(redux_min(fkey(ly)));
    lz = funkey(redux_min(fkey(lz)));
    hx = funkey(redux_max(fkey(hx)));
    hy = funkey(redux_max(fkey(hy)));
    hz = funkey(redux_max(fkey(hz)));
    if (lane == 0) {
        g_clo[ci] = make_float4(lx, ly, lz, 0.0f);
        g_chi[ci] = make_float4(hx, hy, hz, 0.0f);
    }
}

// ---- NN: warp owns 64 sorted queries; streams chunks with bbox pruning ----

__global__ __launch_bounds__(128)
void nn_pass() {
    const int blk  = blockIdx.x;       // 256 = 2 dirs x 4 batches x 32 tiles
    const int dir  = blk >> 7;
    const int b    = (blk >> 5) & 3;
    const int tile = blk & 31;
    const int w    = threadIdx.x >> 5;
    const int lane = threadIdx.x & 31;

    const int qseg = dir * Bn + b;
    const int dseg = qseg ^ Bn;        // other cloud, same batch
    const int qoff = tile * 256 + w * 64;          // position within segment
    const int qa_i = qseg * Np + qoff + lane;
    const int qb_i = qa_i + 32;
    const int db   = dseg * Np;
    const int cb   = dseg * NCH;

    float4 qa = g_pts[qa_i];           // coalesced
    float4 qb = g_pts[qb_i];
    float ax = -2.0f * qa.x, ay = -2.0f * qa.y, az = -2.0f * qa.z;
    float bx = -2.0f * qb.x, by = -2.0f * qb.y, bz = -2.0f * qb.z;

    // warp query bbox (conservative)
    float qlx = funkey(redux_min(fkey(fminf(qa.x, qb.x))));
    float qly = funkey(redux_min(fkey(fminf(qa.y, qb.y))));
    float qlz = funkey(redux_min(fkey(fminf(qa.z, qb.z))));
    float qhx = funkey(redux_max(fkey(fmaxf(qa.x, qb.x))));
    float qhy = funkey(redux_max(fkey(fmaxf(qa.y, qb.y))));
    float qhz = funkey(redux_max(fkey(fmaxf(qa.z, qb.z))));

    float ema = 3.4e38f, emb = 3.4e38f;
    const int cseed = qoff / CHSZ;     // CDF-matched chunk: seeds a tight bound

#pragma unroll 1
    for (int cc = 0; cc <= NCH; cc++) {
        int c;
        if (cc == 0) c = cseed;        // process seed first, unconditionally
        else {
            c = cc - 1;
            if (c == cseed) continue;
            // conservative box-to-box distance lower bound
            float4 lo = g_clo[cb + c];
            float4 hi = g_chi[cb + c];
            float gx = fmaxf(fmaxf(lo.x - qhx, qlx - hi.x), 0.0f);
            float gy = fmaxf(fmaxf(lo.y - qhy, qly - hi.y), 0.0f);
            float gz = fmaxf(fmaxf(lo.z - qhz, qlz - hi.z), 0.0f);
            float d2b = fmaf(gx, gx, fmaf(gy, gy, gz * gz));
            // warp-max of current best d2 (uniform across warp via redux)
            float bnd = funkey(redux_max(fkey(fmaxf(qa.w + ema, qb.w + emb))));
            if (d2b > bnd * 1.001f) continue;   // provably no improving candidate
        }
        const int pb = db + c * CHSZ;
#pragma unroll 8
        for (int u = 0; u < CHSZ; u++) {
            float4 t = g_pts[pb + u];   // uniform address: broadcast LDG
            float ea = fmaf(ax, t.x, fmaf(ay, t.y, fmaf(az, t.z, t.w)));
            float eb = fmaf(bx, t.x, fmaf(by, t.y, fmaf(bz, t.z, t.w)));
            ema = fminf(ema, ea);
            emb = fminf(emb, eb);
        }
    }

    // best d2 = |q|^2 + min(|t|^2 - 2 q.t); write to ORIGINAL index slots
    g_mind[dir * (Bn * Np) + b * Np + g_idx[qa_i]] = qa.w + ema;
    g_mind[dir * (Bn * Np) + b * Np + g_idx[qb_i]] = qb.w + emb;
}

// ---- deterministic fixed-order sum ----

__global__ void final_sum(float* out) {
    __shared__ float sh[1024];
    int tid = threadIdx.x;
    float s = 0.0f;
    for (int i = tid; i < NPTS; i += 1024) s += g_mind[i];  // fixed order
    sh[tid] = s;
    __syncthreads();
#pragma unroll
    for (int st = 512; st > 0; st >>= 1) {
        if (tid < st) sh[tid] += sh[tid + st];
        __syncthreads();
    }
    if (tid == 0)
        out[0] = sh[0] / (float)(Bn * Np);  // (sum_fwd + sum_bwd) / (B*G)
}

extern "C" void kernel_launch(void* const* d_in, const int* in_sizes, int n_in,
                              void* d_out, int out_size) {
    const float* src = (const float*)d_in[0];  // (4, 8192, 3) fp32
    const float* tgt = (const float*)d_in[1];  // (4, 8192, 3) fp32
    float* out = (float*)d_out;

    build_sort<<<NSEG, 1024>>>(src, tgt);
    chunk_bbox<<<(NSEG * NCH) / 8, 256>>>();   // 64 blocks x 8 warps = 512 chunks
    nn_pass<<<256, 128>>>();
    final_sum<<<1, 1024>>>(out);
}